// round 6
// baseline (speedup 1.0000x reference)
#include <cuda_runtime.h>
#include <cuda_bf16.h>

// Problem constants (fixed by reference setup_inputs)
#define MAXN      131072
#define B_SEG     32
#define P_DIM     8
#define TF        256           // T*F = 8*32
#define BP        (B_SEG*P_DIM) // 256
#define CHUNK     96            // nodes per block in accumulate pass (1042 blocks = 1 wave)
#define EPS       1e-16f

// Scratch (no allocations allowed -> device globals)
__device__ float g_e[MAXN * P_DIM];   // e = exp(h)  (no max-subtract; |h| << 88)
__device__ float g_sum[BP];           // sum of e per (seg,p)

// ---------------------------------------------------------------------------
// K0: micro-init — zero g_sum only (1 block)
// ---------------------------------------------------------------------------
__global__ void init_sum_kernel() {
    g_sum[threadIdx.x] = 0.0f;
}

// ---------------------------------------------------------------------------
// K1 (fused): zero out; h = elu(pos@W1+b1)@W2+b2 ; e = exp(h) ; segment sum
//   Fast MUFU transcendentals (__expf); warp shuffle reduction for sums
//   (seg sorted -> warps almost always uniform) + 8 global atomics per warp.
// ---------------------------------------------------------------------------
__global__ void __launch_bounds__(256) mlp_exp_sum_kernel(
    const float* __restrict__ pos, const int* __restrict__ seg,
    const float* __restrict__ W1, const float* __restrict__ b1,
    const float* __restrict__ W2, const float* __restrict__ b2,
    float* __restrict__ out, int out_size, int N)
{
    __shared__ float sW1[24], sb1[8], sW2[64], sb2[8];
    int tid = threadIdx.x;

    // zero the output buffer (grid-stride; independent of the MLP work)
    int gstride = gridDim.x * blockDim.x;
    for (int i = blockIdx.x * blockDim.x + tid; i < out_size; i += gstride)
        out[i] = 0.0f;

    if (tid < 24) sW1[tid] = __ldg(&W1[tid]);
    if (tid < 8)  { sb1[tid] = __ldg(&b1[tid]); sb2[tid] = __ldg(&b2[tid]); }
    if (tid < 64) sW2[tid] = __ldg(&W2[tid]);
    __syncthreads();

    int n = blockIdx.x * 256 + tid;
    unsigned act = __ballot_sync(0xffffffffu, n < N);
    if (n >= N) return;

    int s = __ldg(&seg[n]);
    float p0 = __ldg(&pos[3*n+0]), p1 = __ldg(&pos[3*n+1]), p2 = __ldg(&pos[3*n+2]);
    float hid[8];
#pragma unroll
    for (int j = 0; j < 8; j++) {
        float v = fmaf(p0, sW1[j], fmaf(p1, sW1[8+j], fmaf(p2, sW1[16+j], sb1[j])));
        hid[j] = (v > 0.0f) ? v : (__expf(v) - 1.0f);   // fast ELU (MUFU)
    }
    float e[8];
#pragma unroll
    for (int p = 0; p < 8; p++) {
        float v = sb2[p];
#pragma unroll
        for (int j = 0; j < 8; j++) v = fmaf(hid[j], sW2[j*8+p], v);
        e[p] = __expf(v);                // TAU = 1; |v| << 88, no max-subtract
    }
    float4* dst = (float4*)&g_e[(size_t)8*n];
    dst[0] = make_float4(e[0], e[1], e[2], e[3]);
    dst[1] = make_float4(e[4], e[5], e[6], e[7]);

    int s0 = __shfl_sync(act, s, 0);
    bool uniform_full = (act == 0xffffffffu) && __all_sync(act, s == s0);
    if (uniform_full) {
#pragma unroll
        for (int p = 0; p < 8; p++) {
#pragma unroll
            for (int off = 16; off; off >>= 1)
                e[p] += __shfl_xor_sync(0xffffffffu, e[p], off);
        }
        if ((tid & 31) == 0) {
#pragma unroll
            for (int p = 0; p < 8; p++)
                atomicAdd(&g_sum[s*8+p], e[p]);
        }
    } else {
#pragma unroll
        for (int p = 0; p < 8; p++)
            atomicAdd(&g_sum[s*8+p], e[p]);
    }
}

// ---------------------------------------------------------------------------
// K2: out[b,t,p,f] += x[n,t,f] * w[n,p]     (heavy, HBM-bound pass)
// Block = CHUNK=96 consecutive nodes; thread tid <-> (t,f) cell.
// 8-wide front-batched loads for MLP; 1042 blocks = one full chip wave.
// ---------------------------------------------------------------------------
__device__ __forceinline__ void flush_acc(float* __restrict__ out, int s,
                                          const float acc[8], int tid)
{
    // out index: b*2048 + t*256 + p*32 + f ; tid = t*32 + f
    int base = s * 2048 + (tid >> 5) * 256 + (tid & 31);
#pragma unroll
    for (int p = 0; p < 8; p++)
        atomicAdd(&out[base + p * 32], acc[p]);
}

__device__ __forceinline__ void fma8(float acc[8], float xv, const float* __restrict__ swn)
{
    float4 w0 = *(const float4*)&swn[0];
    float4 w1 = *(const float4*)&swn[4];
    acc[0] = fmaf(xv, w0.x, acc[0]);
    acc[1] = fmaf(xv, w0.y, acc[1]);
    acc[2] = fmaf(xv, w0.z, acc[2]);
    acc[3] = fmaf(xv, w0.w, acc[3]);
    acc[4] = fmaf(xv, w1.x, acc[4]);
    acc[5] = fmaf(xv, w1.y, acc[5]);
    acc[6] = fmaf(xv, w1.z, acc[6]);
    acc[7] = fmaf(xv, w1.w, acc[7]);
}

__global__ void __launch_bounds__(256) accum_kernel(
    const float* __restrict__ x, const int* __restrict__ seg,
    float* __restrict__ out, int N)
{
    __shared__ float ssum[BP];
    __shared__ float sw[CHUNK * 8];
    __shared__ int   sseg[CHUNK];

    int tid  = threadIdx.x;
    int base = blockIdx.x * CHUNK;
    int cnt  = min(CHUNK, N - base);

    ssum[tid] = g_sum[tid];
    __syncthreads();

    // compute w for this chunk into shared (first cnt threads -> one node each)
    if (tid < cnt) {
        int n = base + tid;
        int s = __ldg(&seg[n]);
        sseg[tid] = s;
        const float4* pe = (const float4*)&g_e[(size_t)8*n];
        float4 a = pe[0], b = pe[1];
        float e[8] = {a.x, a.y, a.z, a.w, b.x, b.y, b.z, b.w};
#pragma unroll
        for (int p = 0; p < 8; p++)
            e[p] = e[p] / (ssum[s*8+p] + EPS);
        float4* dst = (float4*)&sw[8*tid];
        dst[0] = make_float4(e[0], e[1], e[2], e[3]);
        dst[1] = make_float4(e[4], e[5], e[6], e[7]);
    }
    __syncthreads();

    const float* xp = x + (size_t)base * TF + tid;
    float acc[8] = {0,0,0,0,0,0,0,0};

    if (cnt == CHUNK && sseg[0] == sseg[CHUNK-1]) {
        // fast path: full chunk, single segment -> branch-free, 8-wide load batches
#pragma unroll
        for (int ib = 0; ib < CHUNK / 8; ib++) {
            float xv[8];
#pragma unroll
            for (int j = 0; j < 8; j++)
                xv[j] = __ldg(&xp[(size_t)(ib*8 + j) * TF]);
#pragma unroll
            for (int j = 0; j < 8; j++)
                fma8(acc, xv[j], &sw[8*(ib*8 + j)]);
        }
        flush_acc(out, sseg[0], acc, tid);
    } else {
        int cur = sseg[0];
        for (int i = 0; i < cnt; i++) {
            int s = sseg[i];
            if (s != cur) {           // boundary (uniform across block)
                flush_acc(out, cur, acc, tid);
#pragma unroll
                for (int p = 0; p < 8; p++) acc[p] = 0.0f;
                cur = s;
            }
            float xv = __ldg(&xp[(size_t)i * TF]);
            fma8(acc, xv, &sw[8*i]);
        }
        flush_acc(out, cur, acc, tid);
    }
}

// ---------------------------------------------------------------------------
extern "C" void kernel_launch(void* const* d_in, const int* in_sizes, int n_in,
                              void* d_out, int out_size)
{
    const float* pos = (const float*)d_in[0];
    const float* x   = (const float*)d_in[1];
    const int*   seg = (const int*)  d_in[2];
    const float* W1  = (const float*)d_in[3];
    const float* b1  = (const float*)d_in[4];
    const float* W2  = (const float*)d_in[5];
    const float* b2  = (const float*)d_in[6];
    float* out = (float*)d_out;

    int N = in_sizes[2];               // seg has one entry per node

    init_sum_kernel<<<1, BP>>>();
    mlp_exp_sum_kernel<<<(N + 255) / 256, 256>>>(pos, seg, W1, b1, W2, b2,
                                                 out, out_size, N);
    accum_kernel<<<(N + CHUNK - 1) / CHUNK, 256>>>(x, seg, out, N);
}

// round 7
// speedup vs baseline: 1.2324x; 1.2324x over previous
#include <cuda_runtime.h>
#include <cuda_bf16.h>

// Problem constants (fixed by reference setup_inputs)
#define MAXN      131072
#define B_SEG     32
#define P_DIM     8
#define TF        256           // T*F = 8*32
#define BP        (B_SEG*P_DIM) // 256
#define CHUNK     64            // nodes per block in accumulate pass (known-good)
#define EPS       1e-16f

// Scratch (no allocations allowed -> device globals)
__device__ float g_e[MAXN * P_DIM];   // e = exp(h)  (no max-subtract; |h| << 88)
__device__ float g_sum[BP];           // sum of e per (seg,p)

// ---------------------------------------------------------------------------
// packed f32x2 helpers (FFMA2 — only reachable via PTX fma.rn.f32x2)
// ---------------------------------------------------------------------------
__device__ __forceinline__ unsigned long long bcast2(float x) {
    unsigned long long r;
    unsigned int u = __float_as_uint(x);
    asm("mov.b64 %0, {%1, %1};" : "=l"(r) : "r"(u));
    return r;
}
__device__ __forceinline__ void fma2(unsigned long long& acc,
                                     unsigned long long a, unsigned long long b) {
    asm("fma.rn.f32x2 %0, %1, %2, %3;" : "=l"(acc) : "l"(a), "l"(b), "l"(acc));
}

// ---------------------------------------------------------------------------
// K0: micro-init — zero g_sum only (1 block)
// ---------------------------------------------------------------------------
__global__ void init_sum_kernel() {
    g_sum[threadIdx.x] = 0.0f;
}

// ---------------------------------------------------------------------------
// K1 (fused): zero out; h = elu(pos@W1+b1)@W2+b2 ; e = exp(h) ; segment sum
//   Fast MUFU transcendentals (__expf); warp shuffle reduction for sums
//   (seg sorted -> warps almost always uniform) + 8 global atomics per warp.
// ---------------------------------------------------------------------------
__global__ void __launch_bounds__(256) mlp_exp_sum_kernel(
    const float* __restrict__ pos, const int* __restrict__ seg,
    const float* __restrict__ W1, const float* __restrict__ b1,
    const float* __restrict__ W2, const float* __restrict__ b2,
    float* __restrict__ out, int out_size, int N)
{
    __shared__ float sW1[24], sb1[8], sW2[64], sb2[8];
    int tid = threadIdx.x;

    // zero the output buffer (grid-stride; one store per thread at this size)
    int gstride = gridDim.x * blockDim.x;
    for (int i = blockIdx.x * blockDim.x + tid; i < out_size; i += gstride)
        out[i] = 0.0f;

    if (tid < 24) sW1[tid] = __ldg(&W1[tid]);
    if (tid < 8)  { sb1[tid] = __ldg(&b1[tid]); sb2[tid] = __ldg(&b2[tid]); }
    if (tid < 64) sW2[tid] = __ldg(&W2[tid]);
    __syncthreads();

    int n = blockIdx.x * 256 + tid;
    unsigned act = __ballot_sync(0xffffffffu, n < N);
    if (n >= N) return;

    int s = __ldg(&seg[n]);
    float p0 = __ldg(&pos[3*n+0]), p1 = __ldg(&pos[3*n+1]), p2 = __ldg(&pos[3*n+2]);
    float hid[8];
#pragma unroll
    for (int j = 0; j < 8; j++) {
        float v = fmaf(p0, sW1[j], fmaf(p1, sW1[8+j], fmaf(p2, sW1[16+j], sb1[j])));
        hid[j] = (v > 0.0f) ? v : (__expf(v) - 1.0f);   // fast ELU (MUFU)
    }
    float e[8];
#pragma unroll
    for (int p = 0; p < 8; p++) {
        float v = sb2[p];
#pragma unroll
        for (int j = 0; j < 8; j++) v = fmaf(hid[j], sW2[j*8+p], v);
        e[p] = __expf(v);                // TAU = 1; |v| << 88, no max-subtract
    }
    float4* dst = (float4*)&g_e[(size_t)8*n];
    dst[0] = make_float4(e[0], e[1], e[2], e[3]);
    dst[1] = make_float4(e[4], e[5], e[6], e[7]);

    int s0 = __shfl_sync(act, s, 0);
    bool uniform_full = (act == 0xffffffffu) && __all_sync(act, s == s0);
    if (uniform_full) {
#pragma unroll
        for (int p = 0; p < 8; p++) {
#pragma unroll
            for (int off = 16; off; off >>= 1)
                e[p] += __shfl_xor_sync(0xffffffffu, e[p], off);
        }
        if ((tid & 31) == 0) {
#pragma unroll
            for (int p = 0; p < 8; p++)
                atomicAdd(&g_sum[s*8+p], e[p]);
        }
    } else {
#pragma unroll
        for (int p = 0; p < 8; p++)
            atomicAdd(&g_sum[s*8+p], e[p]);
    }
}

// ---------------------------------------------------------------------------
// K2: out[b,t,p,f] += x[n,t,f] * w[n,p]     (heavy, HBM-bound pass)
// Block = CHUNK=64 consecutive nodes; thread tid <-> (t,f) cell.
// 8-wide front-batched loads; packed f32x2 accumulators (FFMA2).
// ---------------------------------------------------------------------------
__device__ __forceinline__ void flush_acc2(float* __restrict__ out, int s,
                                           const unsigned long long acc2[4], int tid)
{
    // out index: b*2048 + t*256 + p*32 + f ; tid = t*32 + f
    int base = s * 2048 + (tid >> 5) * 256 + (tid & 31);
#pragma unroll
    for (int k = 0; k < 4; k++) {
        atomicAdd(&out[base + (2*k+0) * 32], __uint_as_float((unsigned int)acc2[k]));
        atomicAdd(&out[base + (2*k+1) * 32], __uint_as_float((unsigned int)(acc2[k] >> 32)));
    }
}

__device__ __forceinline__ void fma8p(unsigned long long acc2[4], float xv,
                                      const float* __restrict__ swn)
{
    unsigned long long xv2 = bcast2(xv);
    const ulonglong2* wv = (const ulonglong2*)swn;   // 16B-aligned (sw aligned)
    ulonglong2 wA = wv[0], wB = wv[1];
    fma2(acc2[0], xv2, wA.x);
    fma2(acc2[1], xv2, wA.y);
    fma2(acc2[2], xv2, wB.x);
    fma2(acc2[3], xv2, wB.y);
}

__global__ void __launch_bounds__(256) accum_kernel(
    const float* __restrict__ x, const int* __restrict__ seg,
    float* __restrict__ out, int N)
{
    __shared__ float ssum[BP];
    __shared__ __align__(16) float sw[CHUNK * 8];
    __shared__ int sseg[CHUNK];

    int tid  = threadIdx.x;
    int base = blockIdx.x * CHUNK;
    int cnt  = min(CHUNK, N - base);

    ssum[tid] = g_sum[tid];
    __syncthreads();

    // compute w for this chunk into shared (first cnt threads -> one node each)
    if (tid < cnt) {
        int n = base + tid;
        int s = __ldg(&seg[n]);
        sseg[tid] = s;
        const float4* pe = (const float4*)&g_e[(size_t)8*n];
        float4 a = pe[0], b = pe[1];
        float e[8] = {a.x, a.y, a.z, a.w, b.x, b.y, b.z, b.w};
#pragma unroll
        for (int p = 0; p < 8; p++)
            e[p] = e[p] / (ssum[s*8+p] + EPS);
        float4* dst = (float4*)&sw[8*tid];
        dst[0] = make_float4(e[0], e[1], e[2], e[3]);
        dst[1] = make_float4(e[4], e[5], e[6], e[7]);
    }
    __syncthreads();

    const float* xp = x + (size_t)base * TF + tid;
    unsigned long long acc2[4] = {0ull, 0ull, 0ull, 0ull};

    if (cnt == CHUNK && sseg[0] == sseg[CHUNK-1]) {
        // fast path: full chunk, single segment -> branch-free, 8-wide load batches
#pragma unroll
        for (int ib = 0; ib < CHUNK / 8; ib++) {
            float xv[8];
#pragma unroll
            for (int j = 0; j < 8; j++)
                xv[j] = __ldg(&xp[(size_t)(ib*8 + j) * TF]);
#pragma unroll
            for (int j = 0; j < 8; j++)
                fma8p(acc2, xv[j], &sw[8*(ib*8 + j)]);
        }
        flush_acc2(out, sseg[0], acc2, tid);
    } else {
        int cur = sseg[0];
        for (int i = 0; i < cnt; i++) {
            int s = sseg[i];
            if (s != cur) {           // boundary (uniform across block)
                flush_acc2(out, cur, acc2, tid);
#pragma unroll
                for (int k = 0; k < 4; k++) acc2[k] = 0ull;
                cur = s;
            }
            float xv = __ldg(&xp[(size_t)i * TF]);
            fma8p(acc2, xv, &sw[8*i]);
        }
        flush_acc2(out, cur, acc2, tid);
    }
}

// ---------------------------------------------------------------------------
extern "C" void kernel_launch(void* const* d_in, const int* in_sizes, int n_in,
                              void* d_out, int out_size)
{
    const float* pos = (const float*)d_in[0];
    const float* x   = (const float*)d_in[1];
    const int*   seg = (const int*)  d_in[2];
    const float* W1  = (const float*)d_in[3];
    const float* b1  = (const float*)d_in[4];
    const float* W2  = (const float*)d_in[5];
    const float* b2  = (const float*)d_in[6];
    float* out = (float*)d_out;

    int N = in_sizes[2];               // seg has one entry per node

    init_sum_kernel<<<1, BP>>>();
    mlp_exp_sum_kernel<<<(N + 255) / 256, 256>>>(pos, seg, W1, b1, W2, b2,
                                                 out, out_size, N);
    accum_kernel<<<(N + CHUNK - 1) / CHUNK, 256>>>(x, seg, out, N);
}